// round 7
// baseline (speedup 1.0000x reference)
#include <cuda_runtime.h>
#include <cstdint>

#define VOCAB  50000
#define EMBED  256
#define MAXLEN 512
#define UNITS  32
#define F1     16
#define BATCH  512

// Scratch: projected embedding table P[v][u] = sum_e emb[v][e]*Wx[e][u], prescaled
// by 2*log2(e) so the recurrence can feed ex2 directly.
__device__ float g_P[VOCAB * UNITS];

#define TANH_SCALE 2.8853900817779268f   // 2*log2(e)

// ---------------------------------------------------------------------------
// Packed f32x2 helpers
// ---------------------------------------------------------------------------
__device__ __forceinline__ unsigned long long pk2(float lo, float hi) {
    unsigned long long r;
    asm("mov.b64 %0, {%1, %2};" : "=l"(r) : "f"(lo), "f"(hi));
    return r;
}
__device__ __forceinline__ void upk2(float& lo, float& hi, unsigned long long v) {
    asm("mov.b64 {%0, %1}, %2;" : "=f"(lo), "=f"(hi) : "l"(v));
}
__device__ __forceinline__ unsigned long long fma2(
    unsigned long long a, unsigned long long b, unsigned long long c) {
    unsigned long long d;
    asm("fma.rn.f32x2 %0, %1, %2, %3;" : "=l"(d) : "l"(a), "l"(b), "l"(c));
    return d;
}
__device__ __forceinline__ unsigned long long mul2(
    unsigned long long a, unsigned long long b) {
    unsigned long long d;
    asm("mul.rn.f32x2 %0, %1, %2;" : "=l"(d) : "l"(a), "l"(b));
    return d;
}
__device__ __forceinline__ unsigned long long add2(
    unsigned long long a, unsigned long long b) {
    unsigned long long d;
    asm("add.rn.f32x2 %0, %1, %2;" : "=l"(d) : "l"(a), "l"(b));
    return d;
}

// ---------------------------------------------------------------------------
// Kernel A: P = (emb_table @ Wx) * TANH_SCALE, packed f32x2 version.
// Wx pre-packed in SMEM over e-pairs: sW2[e2*32+u] = {Wx[2e2][u], Wx[2e2+1][u]}.
// A rows loaded as float4 (4 consecutive e) -> two packed pairs for free.
// Each acc is a packed partial sum {even-e, odd-e}; horizontal add at the end.
// ---------------------------------------------------------------------------
__global__ void __launch_bounds__(128) proj_kernel(
    const float* __restrict__ emb, const float* __restrict__ Wx)
{
    __shared__ unsigned long long sW2[(EMBED / 2) * UNITS];   // 32 KB
    const int t = threadIdx.x;
    for (int i = t; i < (EMBED / 2) * UNITS; i += 128) {
        const int e2 = i >> 5, u = i & 31;
        sW2[i] = pk2(Wx[(2 * e2) * UNITS + u], Wx[(2 * e2 + 1) * UNITS + u]);
    }
    __syncthreads();

    const int ug    = t & 3;          // u-group: units ug*8 .. ug*8+7
    const int s     = t >> 2;         // row-set
    const int rbase = blockIdx.x * 128 + s * 4;

    unsigned long long acc[4][8];
    #pragma unroll
    for (int rr = 0; rr < 4; rr++)
        #pragma unroll
        for (int j = 0; j < 8; j++) acc[rr][j] = 0ull;

    const float* arow[4];
    #pragma unroll
    for (int rr = 0; rr < 4; rr++) {
        int r = rbase + rr;
        if (r >= VOCAB) r = VOCAB - 1;            // clamp; stores guarded
        arow[rr] = emb + (size_t)r * EMBED;
    }

    for (int e0 = 0; e0 < EMBED; e0 += 4) {
        float4 av[4];
        #pragma unroll
        for (int rr = 0; rr < 4; rr++)
            av[rr] = *(const float4*)(arow[rr] + e0);

        #pragma unroll
        for (int ep = 0; ep < 2; ep++) {
            const int e2 = (e0 >> 1) + ep;
            const ulonglong2* wr = (const ulonglong2*)&sW2[e2 * UNITS + ug * 8];
            const ulonglong2 w01 = wr[0], w23 = wr[1], w45 = wr[2], w67 = wr[3];
            #pragma unroll
            for (int rr = 0; rr < 4; rr++) {
                const float a0 = (ep == 0) ? av[rr].x : av[rr].z;
                const float a1 = (ep == 0) ? av[rr].y : av[rr].w;
                const unsigned long long ap = pk2(a0, a1);
                acc[rr][0] = fma2(ap, w01.x, acc[rr][0]);
                acc[rr][1] = fma2(ap, w01.y, acc[rr][1]);
                acc[rr][2] = fma2(ap, w23.x, acc[rr][2]);
                acc[rr][3] = fma2(ap, w23.y, acc[rr][3]);
                acc[rr][4] = fma2(ap, w45.x, acc[rr][4]);
                acc[rr][5] = fma2(ap, w45.y, acc[rr][5]);
                acc[rr][6] = fma2(ap, w67.x, acc[rr][6]);
                acc[rr][7] = fma2(ap, w67.y, acc[rr][7]);
            }
        }
    }

    #pragma unroll
    for (int rr = 0; rr < 4; rr++) {
        const int r = rbase + rr;
        if (r < VOCAB) {
            float o[8];
            #pragma unroll
            for (int j = 0; j < 8; j++) {
                float lo, hi;
                upk2(lo, hi, acc[rr][j]);
                o[j] = (lo + hi) * TANH_SCALE;
            }
            *(float4*)&g_P[r * UNITS + ug * 8]     = make_float4(o[0], o[1], o[2], o[3]);
            *(float4*)&g_P[r * UNITS + ug * 8 + 4] = make_float4(o[4], o[5], o[6], o[7]);
        }
    }
}

// ---------------------------------------------------------------------------
// Kernel B: recurrence + head. One warp per batch row, lane u owns unit u.
// State r = 1/(1+e^(2x)) (h = 1-2r); affine folded into weights.
// Broadcast via SMEM (1 STS + syncwarp + 8 LDS.128 broadcast); matvec as
// 16 packed fma2 into 8 accs + packed tree.
// Prefetch is GROUPED: per 4-step group, one int4 token load + 4 consecutive
// LDGs into a ping-pong buffer, so their scoreboard wait lands only at the
// next group boundary and never aliases the per-step LDS waits.
// ---------------------------------------------------------------------------
__global__ void __launch_bounds__(128, 1) rnn_kernel(
    const int*   __restrict__ tokens,
    const float* __restrict__ Wh,
    const float* __restrict__ bvec,
    const float* __restrict__ W1,
    const float* __restrict__ b1,
    const float* __restrict__ W2,
    const float* __restrict__ b2,
    float*       __restrict__ out)
{
    __shared__ int   sTok[4 * MAXLEN];
    __shared__ float sR[4][32];             // 128B row per warp, 16B aligned

    const int tid  = threadIdx.x;
    const int wid  = tid >> 5;
    const int lane = tid & 31;
    const int b0   = blockIdx.x * 4;

    for (int i = tid; i < 4 * MAXLEN; i += 128)
        sTok[i] = tokens[b0 * MAXLEN + i];
    __syncthreads();

    const int4* myTok4 = (const int4*)(sTok + wid * MAXLEN);  // 16B-aligned
    const int   brow   = b0 + wid;

    // Packed column weights: wpk[k] = {-2S*Wh[2k][lane], -2S*Wh[2k+1][lane]}
    unsigned long long wpk[16];
    float cs = 0.f;
    #pragma unroll
    for (int v = 0; v < 32; v += 2) {
        const float w0 = Wh[v * UNITS + lane];
        const float w1 = Wh[(v + 1) * UNITS + lane];
        cs += w0 + w1;
        wpk[v >> 1] = pk2(w0 * (-2.0f * TANH_SCALE), w1 * (-2.0f * TANH_SCALE));
    }
    const float cbias = (bvec[lane] + cs) * TANH_SCALE;

    float* sRrow = sR[wid];
    const ulonglong2* rrow = (const ulonglong2*)sRrow;   // 8 x 16B

    const int NG = MAXLEN / 4;              // 128 groups of 4 steps

    // Prime group 0: tokens + 4 P-row loads.
    int4  tk = myTok4[0];
    float c0 = g_P[tk.x * UNITS + lane];
    float c1 = g_P[tk.y * UNITS + lane];
    float c2 = g_P[tk.z * UNITS + lane];
    float c3 = g_P[tk.w * UNITS + lane];

    float r = 0.5f;                         // h = 1 - 2r = 0
    for (int g = 0; g < NG; g++) {
        // Issue next group's prefetch: 1 LDS.128 + 4 consecutive LDG.32.
        const int gn = (g + 1 < NG) ? (g + 1) : g;        // uniform clamp
        const int4 tkn = myTok4[gn];
        const float n0 = g_P[tkn.x * UNITS + lane];
        const float n1 = g_P[tkn.y * UNITS + lane];
        const float n2 = g_P[tkn.z * UNITS + lane];
        const float n3 = g_P[tkn.w * UNITS + lane];

        // Precompute packed seeds {xw + cbias, 0} for the 4 steps (off-path).
        unsigned long long seed[4];
        seed[0] = pk2(c0 + cbias, 0.f);
        seed[1] = pk2(c1 + cbias, 0.f);
        seed[2] = pk2(c2 + cbias, 0.f);
        seed[3] = pk2(c3 + cbias, 0.f);

        #pragma unroll
        for (int j = 0; j < 4; j++) {
            sRrow[lane] = r;
            __syncwarp();

            const ulonglong2 q0 = rrow[0];
            const ulonglong2 q1 = rrow[1];
            const ulonglong2 q2 = rrow[2];
            const ulonglong2 q3 = rrow[3];
            const ulonglong2 q4 = rrow[4];
            const ulonglong2 q5 = rrow[5];
            const ulonglong2 q6 = rrow[6];
            const ulonglong2 q7 = rrow[7];

            unsigned long long a0 = fma2(q0.x, wpk[0],  seed[j]);
            unsigned long long a1 = mul2(q1.x, wpk[2]);
            unsigned long long a2 = mul2(q2.x, wpk[4]);
            unsigned long long a3 = mul2(q3.x, wpk[6]);
            unsigned long long a4 = mul2(q4.x, wpk[8]);
            unsigned long long a5 = mul2(q5.x, wpk[10]);
            unsigned long long a6 = mul2(q6.x, wpk[12]);
            unsigned long long a7 = mul2(q7.x, wpk[14]);
            a0 = fma2(q0.y, wpk[1],  a0);
            a1 = fma2(q1.y, wpk[3],  a1);
            a2 = fma2(q2.y, wpk[5],  a2);
            a3 = fma2(q3.y, wpk[7],  a3);
            a4 = fma2(q4.y, wpk[9],  a4);
            a5 = fma2(q5.y, wpk[11], a5);
            a6 = fma2(q6.y, wpk[13], a6);
            a7 = fma2(q7.y, wpk[15], a7);

            const unsigned long long s0 = add2(a0, a1);
            const unsigned long long s1 = add2(a2, a3);
            const unsigned long long s2 = add2(a4, a5);
            const unsigned long long s3 = add2(a6, a7);
            const unsigned long long t1 = add2(s0, s1);
            const unsigned long long t2 = add2(s2, s3);
            const unsigned long long u  = add2(t1, t2);
            float lo, hi;
            upk2(lo, hi, u);
            const float z2 = lo + hi;       // = 2*log2(e) * preact
            float e, rn;
            asm("ex2.approx.f32 %0, %1;" : "=f"(e) : "f"(z2));
            asm("rcp.approx.f32 %0, %1;" : "=f"(rn) : "f"(e + 1.0f));
            r = rn;
        }

        // Rotate ping-pong buffers (waits on this group's 4 LDGs here).
        c0 = n0; c1 = n1; c2 = n2; c3 = n3;
    }

    const float h = fmaf(-2.0f, r, 1.0f);   // final hidden value for lane

    // Head: f = h@W1 + b1 (16), z = f@W2 + b2, out = sigmoid(z)  (one-time)
    float facc = 0.f;
    #pragma unroll
    for (int v = 0; v < 32; v++) {
        const float hv = __shfl_sync(0xffffffffu, h, v);
        if (lane < F1)
            facc = fmaf(hv, W1[v * F1 + lane], facc);
    }
    float p = 0.f;
    if (lane < F1) p = (facc + b1[lane]) * W2[lane];
    #pragma unroll
    for (int off = 16; off > 0; off >>= 1)
        p += __shfl_xor_sync(0xffffffffu, p, off);

    if (lane == 0) {
        const float z = p + b2[0];
        float e, rr;
        asm("ex2.approx.f32 %0, %1;" : "=f"(e) : "f"(-z * 1.4426950408889634f));
        asm("rcp.approx.f32 %0, %1;" : "=f"(rr) : "f"(1.0f + e));
        out[brow] = rr;
    }
}

// ---------------------------------------------------------------------------
extern "C" void kernel_launch(void* const* d_in, const int* in_sizes, int n_in,
                              void* d_out, int out_size)
{
    const int*   tokens = (const int*)  d_in[0];
    const float* emb    = (const float*)d_in[1];
    const float* Wx     = (const float*)d_in[2];
    const float* Wh     = (const float*)d_in[3];
    const float* b      = (const float*)d_in[4];
    const float* W1     = (const float*)d_in[5];
    const float* b1     = (const float*)d_in[6];
    const float* W2     = (const float*)d_in[7];
    const float* b2     = (const float*)d_in[8];
    float* out = (float*)d_out;

    proj_kernel<<<(VOCAB + 127) / 128, 128>>>(emb, Wx);
    rnn_kernel<<<BATCH / 4, 128>>>(tokens, Wh, b, W1, b1, W2, b2, out);
}

// round 8
// speedup vs baseline: 1.0865x; 1.0865x over previous
#include <cuda_runtime.h>
#include <cstdint>

#define VOCAB  50000
#define EMBED  256
#define MAXLEN 512
#define UNITS  32
#define F1     16
#define BATCH  512

// Scratch: projected embedding table P[v][u] = sum_e emb[v][e]*Wx[e][u], prescaled
// by 2*log2(e) so the recurrence can feed ex2 directly.
__device__ float g_P[VOCAB * UNITS];

#define TANH_SCALE 2.8853900817779268f   // 2*log2(e)

// ---------------------------------------------------------------------------
// Packed f32x2 helpers
// ---------------------------------------------------------------------------
__device__ __forceinline__ unsigned long long pk2(float lo, float hi) {
    unsigned long long r;
    asm("mov.b64 %0, {%1, %2};" : "=l"(r) : "f"(lo), "f"(hi));
    return r;
}
__device__ __forceinline__ void upk2(float& lo, float& hi, unsigned long long v) {
    asm("mov.b64 {%0, %1}, %2;" : "=f"(lo), "=f"(hi) : "l"(v));
}
__device__ __forceinline__ unsigned long long fma2(
    unsigned long long a, unsigned long long b, unsigned long long c) {
    unsigned long long d;
    asm("fma.rn.f32x2 %0, %1, %2, %3;" : "=l"(d) : "l"(a), "l"(b), "l"(c));
    return d;
}
__device__ __forceinline__ unsigned long long mul2(
    unsigned long long a, unsigned long long b) {
    unsigned long long d;
    asm("mul.rn.f32x2 %0, %1, %2;" : "=l"(d) : "l"(a), "l"(b));
    return d;
}
__device__ __forceinline__ unsigned long long add2(
    unsigned long long a, unsigned long long b) {
    unsigned long long d;
    asm("add.rn.f32x2 %0, %1, %2;" : "=l"(d) : "l"(a), "l"(b));
    return d;
}

// ---------------------------------------------------------------------------
// Kernel A: P = (emb_table @ Wx) * TANH_SCALE  (R1 scalar version, 13us —
// the packed variant regressed to 26us, reverted)
// ---------------------------------------------------------------------------
__global__ void __launch_bounds__(128) proj_kernel(
    const float* __restrict__ emb, const float* __restrict__ Wx)
{
    __shared__ float sW[EMBED * UNITS];
    const int t = threadIdx.x;
    for (int i = t; i < EMBED * UNITS / 4; i += 128)
        ((float4*)sW)[i] = ((const float4*)Wx)[i];
    __syncthreads();

    const int ug    = t & 3;
    const int s     = t >> 2;
    const int rbase = blockIdx.x * 128 + s * 4;

    float acc[4][8];
    #pragma unroll
    for (int rr = 0; rr < 4; rr++)
        #pragma unroll
        for (int j = 0; j < 8; j++) acc[rr][j] = 0.f;

    const float* arow[4];
    #pragma unroll
    for (int rr = 0; rr < 4; rr++) {
        int r = rbase + rr;
        if (r >= VOCAB) r = VOCAB - 1;
        arow[rr] = emb + (size_t)r * EMBED;
    }

    for (int e0 = 0; e0 < EMBED; e0 += 4) {
        float4 av[4];
        #pragma unroll
        for (int rr = 0; rr < 4; rr++)
            av[rr] = *(const float4*)(arow[rr] + e0);

        #pragma unroll
        for (int ee = 0; ee < 4; ee++) {
            const float4 w0 = *(const float4*)&sW[(e0 + ee) * UNITS + ug * 8];
            const float4 w1 = *(const float4*)&sW[(e0 + ee) * UNITS + ug * 8 + 4];
            #pragma unroll
            for (int rr = 0; rr < 4; rr++) {
                const float a = ((const float*)&av[rr])[ee];
                acc[rr][0] = fmaf(a, w0.x, acc[rr][0]);
                acc[rr][1] = fmaf(a, w0.y, acc[rr][1]);
                acc[rr][2] = fmaf(a, w0.z, acc[rr][2]);
                acc[rr][3] = fmaf(a, w0.w, acc[rr][3]);
                acc[rr][4] = fmaf(a, w1.x, acc[rr][4]);
                acc[rr][5] = fmaf(a, w1.y, acc[rr][5]);
                acc[rr][6] = fmaf(a, w1.z, acc[rr][6]);
                acc[rr][7] = fmaf(a, w1.w, acc[rr][7]);
            }
        }
    }

    #pragma unroll
    for (int rr = 0; rr < 4; rr++) {
        const int r = rbase + rr;
        if (r < VOCAB) {
            float4 o0, o1;
            o0.x = acc[rr][0] * TANH_SCALE; o0.y = acc[rr][1] * TANH_SCALE;
            o0.z = acc[rr][2] * TANH_SCALE; o0.w = acc[rr][3] * TANH_SCALE;
            o1.x = acc[rr][4] * TANH_SCALE; o1.y = acc[rr][5] * TANH_SCALE;
            o1.z = acc[rr][6] * TANH_SCALE; o1.w = acc[rr][7] * TANH_SCALE;
            *(float4*)&g_P[r * UNITS + ug * 8]     = o0;
            *(float4*)&g_P[r * UNITS + ug * 8 + 4] = o1;
        }
    }
}

// ---------------------------------------------------------------------------
// Kernel B: recurrence + head. One warp per batch row, lane u owns unit u.
// State r = 1/(1+e^(2x)) (h = 1-2r); affine folded into weights.
// Broadcast via SMEM with NO WARPSYNC: within a non-divergent warp the LSU
// processes smem ops in issue order, so STS -> LDS RAW to the same row is
// safe; compiler ordering enforced by volatile asm with memory clobbers.
// ld.shared.v2.b64 yields the packed 64-bit operand pairs fma2 wants.
// ---------------------------------------------------------------------------
__global__ void __launch_bounds__(128, 1) rnn_kernel(
    const int*   __restrict__ tokens,
    const float* __restrict__ Wh,
    const float* __restrict__ bvec,
    const float* __restrict__ W1,
    const float* __restrict__ b1,
    const float* __restrict__ W2,
    const float* __restrict__ b2,
    float*       __restrict__ out)
{
    __shared__ int   sTok[4 * MAXLEN];
    __shared__ float sR[4][32];             // 128B row per warp, 16B aligned

    const int tid  = threadIdx.x;
    const int wid  = tid >> 5;
    const int lane = tid & 31;
    const int b0   = blockIdx.x * 4;

    for (int i = tid; i < 4 * MAXLEN; i += 128)
        sTok[i] = tokens[b0 * MAXLEN + i];
    __syncthreads();

    const int4* myTok4 = (const int4*)(sTok + wid * MAXLEN);  // 16B-aligned
    const int   brow   = b0 + wid;

    // Packed column weights: wpk[k] = {-2S*Wh[2k][lane], -2S*Wh[2k+1][lane]}
    unsigned long long wpk[16];
    float cs = 0.f;
    #pragma unroll
    for (int v = 0; v < 32; v += 2) {
        const float w0 = Wh[v * UNITS + lane];
        const float w1 = Wh[(v + 1) * UNITS + lane];
        cs += w0 + w1;
        wpk[v >> 1] = pk2(w0 * (-2.0f * TANH_SCALE), w1 * (-2.0f * TANH_SCALE));
    }
    const float cbias = (bvec[lane] + cs) * TANH_SCALE;

    const uint32_t rowAddr = (uint32_t)__cvta_generic_to_shared(&sR[wid][0]);
    const uint32_t stAddr  = rowAddr + lane * 4u;

    const int NG = MAXLEN / 4;              // 128 groups of 4 steps

    // Prime group 0: tokens + 4 P-row loads.
    int4  tk = myTok4[0];
    float c0 = g_P[tk.x * UNITS + lane];
    float c1 = g_P[tk.y * UNITS + lane];
    float c2 = g_P[tk.z * UNITS + lane];
    float c3 = g_P[tk.w * UNITS + lane];

    float r = 0.5f;                         // h = 1 - 2r = 0
    for (int g = 0; g < NG; g++) {
        // Issue next group's prefetch: 1 LDS.128 + 4 consecutive LDG.32.
        const int gn = (g + 1 < NG) ? (g + 1) : g;        // uniform clamp
        const int4 tkn = myTok4[gn];
        const float n0 = g_P[tkn.x * UNITS + lane];
        const float n1 = g_P[tkn.y * UNITS + lane];
        const float n2 = g_P[tkn.z * UNITS + lane];
        const float n3 = g_P[tkn.w * UNITS + lane];

        // Precompute packed seeds {xw + cbias, 0} for the 4 steps (off-path).
        unsigned long long seed[4];
        seed[0] = pk2(c0 + cbias, 0.f);
        seed[1] = pk2(c1 + cbias, 0.f);
        seed[2] = pk2(c2 + cbias, 0.f);
        seed[3] = pk2(c3 + cbias, 0.f);

        #pragma unroll
        for (int j = 0; j < 4; j++) {
            // Lane-broadcast through smem, no warpsync: same-warp in-order LSU.
            asm volatile("st.shared.f32 [%0], %1;" :: "r"(stAddr), "f"(r) : "memory");

            unsigned long long q0x, q0y, q1x, q1y, q2x, q2y, q3x, q3y;
            unsigned long long q4x, q4y, q5x, q5y, q6x, q6y, q7x, q7y;
            asm volatile("ld.shared.v2.b64 {%0, %1}, [%2];"
                         : "=l"(q0x), "=l"(q0y) : "r"(rowAddr)        : "memory");
            asm volatile("ld.shared.v2.b64 {%0, %1}, [%2];"
                         : "=l"(q1x), "=l"(q1y) : "r"(rowAddr + 16u)  : "memory");
            asm volatile("ld.shared.v2.b64 {%0, %1}, [%2];"
                         : "=l"(q2x), "=l"(q2y) : "r"(rowAddr + 32u)  : "memory");
            asm volatile("ld.shared.v2.b64 {%0, %1}, [%2];"
                         : "=l"(q3x), "=l"(q3y) : "r"(rowAddr + 48u)  : "memory");
            asm volatile("ld.shared.v2.b64 {%0, %1}, [%2];"
                         : "=l"(q4x), "=l"(q4y) : "r"(rowAddr + 64u)  : "memory");
            asm volatile("ld.shared.v2.b64 {%0, %1}, [%2];"
                         : "=l"(q5x), "=l"(q5y) : "r"(rowAddr + 80u)  : "memory");
            asm volatile("ld.shared.v2.b64 {%0, %1}, [%2];"
                         : "=l"(q6x), "=l"(q6y) : "r"(rowAddr + 96u)  : "memory");
            asm volatile("ld.shared.v2.b64 {%0, %1}, [%2];"
                         : "=l"(q7x), "=l"(q7y) : "r"(rowAddr + 112u) : "memory");

            unsigned long long a0 = fma2(q0x, wpk[0],  seed[j]);
            unsigned long long a1 = mul2(q1x, wpk[2]);
            unsigned long long a2 = mul2(q2x, wpk[4]);
            unsigned long long a3 = mul2(q3x, wpk[6]);
            unsigned long long a4 = mul2(q4x, wpk[8]);
            unsigned long long a5 = mul2(q5x, wpk[10]);
            unsigned long long a6 = mul2(q6x, wpk[12]);
            unsigned long long a7 = mul2(q7x, wpk[14]);
            a0 = fma2(q0y, wpk[1],  a0);
            a1 = fma2(q1y, wpk[3],  a1);
            a2 = fma2(q2y, wpk[5],  a2);
            a3 = fma2(q3y, wpk[7],  a3);
            a4 = fma2(q4y, wpk[9],  a4);
            a5 = fma2(q5y, wpk[11], a5);
            a6 = fma2(q6y, wpk[13], a6);
            a7 = fma2(q7y, wpk[15], a7);

            const unsigned long long s0 = add2(a0, a1);
            const unsigned long long s1 = add2(a2, a3);
            const unsigned long long s2 = add2(a4, a5);
            const unsigned long long s3 = add2(a6, a7);
            const unsigned long long t1 = add2(s0, s1);
            const unsigned long long t2 = add2(s2, s3);
            const unsigned long long u  = add2(t1, t2);
            float lo, hi;
            upk2(lo, hi, u);
            const float z2 = lo + hi;       // = 2*log2(e) * preact
            float e, rn;
            asm("ex2.approx.f32 %0, %1;" : "=f"(e) : "f"(z2));
            asm("rcp.approx.f32 %0, %1;" : "=f"(rn) : "f"(e + 1.0f));
            r = rn;
        }

        // Rotate ping-pong buffers (waits on this group's 4 LDGs here).
        c0 = n0; c1 = n1; c2 = n2; c3 = n3;
    }

    const float h = fmaf(-2.0f, r, 1.0f);   // final hidden value for lane

    // Head: f = h@W1 + b1 (16), z = f@W2 + b2, out = sigmoid(z)  (one-time)
    float facc = 0.f;
    #pragma unroll
    for (int v = 0; v < 32; v++) {
        const float hv = __shfl_sync(0xffffffffu, h, v);
        if (lane < F1)
            facc = fmaf(hv, W1[v * F1 + lane], facc);
    }
    float p = 0.f;
    if (lane < F1) p = (facc + b1[lane]) * W2[lane];
    #pragma unroll
    for (int off = 16; off > 0; off >>= 1)
        p += __shfl_xor_sync(0xffffffffu, p, off);

    if (lane == 0) {
        const float z = p + b2[0];
        float e, rr;
        asm("ex2.approx.f32 %0, %1;" : "=f"(e) : "f"(-z * 1.4426950408889634f));
        asm("rcp.approx.f32 %0, %1;" : "=f"(rr) : "f"(1.0f + e));
        out[brow] = rr;
    }
}

// ---------------------------------------------------------------------------
extern "C" void kernel_launch(void* const* d_in, const int* in_sizes, int n_in,
                              void* d_out, int out_size)
{
    const int*   tokens = (const int*)  d_in[0];
    const float* emb    = (const float*)d_in[1];
    const float* Wx     = (const float*)d_in[2];
    const float* Wh     = (const float*)d_in[3];
    const float* b      = (const float*)d_in[4];
    const float* W1     = (const float*)d_in[5];
    const float* b1     = (const float*)d_in[6];
    const float* W2     = (const float*)d_in[7];
    const float* b2     = (const float*)d_in[8];
    float* out = (float*)d_out;

    proj_kernel<<<(VOCAB + 127) / 128, 128>>>(emb, Wx);
    rnn_kernel<<<BATCH / 4, 128>>>(tokens, Wh, b, W1, b1, W2, b2, out);
}